// round 15
// baseline (speedup 1.0000x reference)
#include <cuda_runtime.h>
#include <cuda_fp16.h>
#include <cstdint>
#include <cstddef>

// Problem constants
#define BB    8
#define NN    1024
#define DD    512
#define HH    8
#define HD    64
#define FFD   2048
#define LL    6
#define CC    5
#define DIN   64
#define MTOT  (BB*NN)   // 8192
#define QKVD  (3*DD)    // 1536

// ---------------- static scratch (no allocations allowed) ----------------
__device__ float g_x [MTOT*DD];
__device__ float g_q [MTOT*DD];     // attn out-proj + residual (fp32, pre-LN)
__device__ float g_t [MTOT*DD];     // FF2 + residual (fp32, pre-LN)

// fp16 buffers
__device__ __half g_qkv[(size_t)MTOT*QKVD];
__device__ __half g_xh [MTOT*DD];
__device__ __half g_th [MTOT*DD];
__device__ __half g_ffh[(size_t)MTOT*FFD];
__device__ __half g_sh [MTOT*DIN];
__device__ __half g_wqkvh[(size_t)LL*QKVD*DD];
__device__ float  g_bqkv [LL*QKVD];
__device__ __half g_woh[LL*DD*DD];
__device__ __half g_w1h[(size_t)LL*FFD*DD];
__device__ __half g_w2h[(size_t)LL*DD*FFD];
__device__ __half g_ewh[DD*DIN];

// ================= helpers =================
__device__ __forceinline__ uint32_t smem_u32(const void* p) {
    uint32_t a;
    asm("{ .reg .u64 t; cvta.to.shared.u64 t, %1; cvt.u32.u64 %0, t; }" : "=r"(a) : "l"(p));
    return a;
}
__device__ __forceinline__ void ldsm_x4(uint32_t* r, uint32_t addr) {
    asm volatile("ldmatrix.sync.aligned.m8n8.x4.shared.b16 {%0,%1,%2,%3}, [%4];"
                 : "=r"(r[0]), "=r"(r[1]), "=r"(r[2]), "=r"(r[3]) : "r"(addr));
}
__device__ __forceinline__ void ldsm_x4_t(uint32_t* r, uint32_t addr) {
    asm volatile("ldmatrix.sync.aligned.m8n8.x4.trans.shared.b16 {%0,%1,%2,%3}, [%4];"
                 : "=r"(r[0]), "=r"(r[1]), "=r"(r[2]), "=r"(r[3]) : "r"(addr));
}
__device__ __forceinline__ void mma_f16(float* d, const uint32_t* a, const uint32_t* b) {
    asm volatile(
        "mma.sync.aligned.m16n8k16.row.col.f32.f16.f16.f32 "
        "{%0,%1,%2,%3}, {%4,%5,%6,%7}, {%8,%9}, {%0,%1,%2,%3};"
        : "+f"(d[0]), "+f"(d[1]), "+f"(d[2]), "+f"(d[3])
        : "r"(a[0]), "r"(a[1]), "r"(a[2]), "r"(a[3]), "r"(b[0]), "r"(b[1]));
}
__device__ __forceinline__ void cpa16(uint32_t dst, const void* src) {
    asm volatile("cp.async.ca.shared.global [%0], [%1], 16;"
                 :: "r"(dst), "l"(__cvta_generic_to_global(src)));
}
__device__ __forceinline__ void cp_commit() {
    asm volatile("cp.async.commit_group;");
}
template<int N> __device__ __forceinline__ void cp_wait() {
    asm volatile("cp.async.wait_group %0;" :: "n"(N));
}
__device__ __forceinline__ uint32_t pack_hf(float a, float b) {
    __half2 p = __floats2half2_rn(a, b);
    return *(uint32_t*)&p;
}

// ---------------- merged fp32 -> fp16 conversion (5 segments in one launch) ----
__global__ void __launch_bounds__(256) conv_multi(
    const float* __restrict__ i0, __half* __restrict__ o0, int n0,
    const float* __restrict__ i1, __half* __restrict__ o1, int n1,
    const float* __restrict__ i2, __half* __restrict__ o2, int n2,
    const float* __restrict__ i3, __half* __restrict__ o3, int n3,
    const float* __restrict__ i4, __half* __restrict__ o4, int n4)
{
    int i = blockIdx.x * blockDim.x + threadIdx.x;
    const float* in; __half* out; int idx;
    if (i < n0)                    { in = i0; out = o0; idx = i; }
    else if ((i -= n0) < n1)       { in = i1; out = o1; idx = i; }
    else if ((i -= n1) < n2)       { in = i2; out = o2; idx = i; }
    else if ((i -= n2) < n3)       { in = i3; out = o3; idx = i; }
    else if ((i -= n3) < n4)       { in = i4; out = o4; idx = i; }
    else return;
    float4 v = ((const float4*)in)[idx];
    uint2 hv;
    hv.x = pack_hf(v.x, v.y);
    hv.y = pack_hf(v.z, v.w);
    ((uint2*)out)[idx] = hv;
}

// ---------------- fused QKV weight convert: [L][3][D][D] from Wq/Wk/Wv ----
__global__ void __launch_bounds__(256) conv_qkv(
    const float* __restrict__ Wq, const float* __restrict__ Wk,
    const float* __restrict__ Wv, __half* __restrict__ out, int n4)
{
    int i = blockIdx.x * blockDim.x + threadIdx.x;
    if (i >= n4) return;
    const int per_mat = DD * DD / 4;
    int l = i / (3 * per_mat);
    int rem = i - l * (3 * per_mat);
    int which = rem / per_mat;
    int r2 = rem - which * per_mat;
    const float* src = (which == 0 ? Wq : (which == 1 ? Wk : Wv)) + (size_t)l * DD * DD;
    float4 v = ((const float4*)src)[r2];
    uint2 hv;
    hv.x = pack_hf(v.x, v.y);
    hv.y = pack_hf(v.z, v.w);
    ((uint2*)out)[i] = hv;
}

// ---------------- concat qkv biases ----------------
__global__ void __launch_bounds__(256) concat_bias(
    const float* __restrict__ bq, const float* __restrict__ bk,
    const float* __restrict__ bv, float* __restrict__ out)
{
    int idx = blockIdx.x * blockDim.x + threadIdx.x;
    if (idx >= LL * QKVD) return;
    int l = idx / QKVD, r = idx % QKVD;
    float v = (r < DD) ? bq[l * DD + r]
            : (r < 2 * DD) ? bk[l * DD + r - DD]
            : bv[l * DD + r - 2 * DD];
    out[idx] = v;
}

// ================== pipelined plain-fp16 GEMM ==================
// BM=128 BN=128 BK=64, 256 threads = 8 warps (4m x 2n), warp tile 32x64.
// 3-stage cp.async pipeline, 108KB SMEM -> 2 CTAs/SM.
// Optional fused residual add (Res, fp32) on the fp32 output path.
#define SSTR    72
#define TILEB   (128*SSTR*2)       // 18432 B
#define STAGEB  (2*TILEB)          // 36864 B
#define NST     3
#define GB_SMEM (NST*STAGEB)       // 110592 B

__global__ void __launch_bounds__(256, 2) gemm_hf(
    int M, int N, int K,
    const __half* __restrict__ Ah,
    const __half* __restrict__ Bh,
    const float* __restrict__ bias,
    const float* __restrict__ Res,
    float* __restrict__ C,
    __half* __restrict__ Ch,
    int relu, int wf32, int wbf)
{
    extern __shared__ char smem[];
    uint32_t sbase = smem_u32(smem);

    int tid  = threadIdx.x;
    int lane = tid & 31;
    int wid  = tid >> 5;
    int wr   = wid >> 1;
    int wc   = wid & 1;
    int g    = lane >> 3;
    int lr   = lane & 7;

    int row0 = blockIdx.y << 7;
    int col0 = blockIdx.x << 7;

    float acc[2][8][4];
#pragma unroll
    for (int mi = 0; mi < 2; mi++)
#pragma unroll
        for (int ni = 0; ni < 8; ni++)
#pragma unroll
            for (int u = 0; u < 4; u++) acc[mi][ni][u] = 0.f;

    uint32_t a_off = (uint32_t)(((wr * 32 + (g & 1) * 8 + lr) * SSTR + (g >> 1) * 8) * 2);
    uint32_t b_off = (uint32_t)(((wc * 64 + (g >> 1) * 8 + lr) * SSTR + (g & 1) * 8) * 2);

    const int nch = K >> 6;

    auto load_chunk = [&](int c, int stg) {
        uint32_t sb = sbase + (uint32_t)stg * STAGEB;
        int k0 = c << 6;
#pragma unroll
        for (int t = 0; t < 4; t++) {
            int i = tid + 256 * t;
            int row = i >> 3;
            int c8  = (i & 7) << 3;
            uint32_t doff = (uint32_t)((row * SSTR + c8) * 2);
            cpa16(sb + doff,         Ah + (size_t)(row0 + row) * K + k0 + c8);
            cpa16(sb + TILEB + doff, Bh + (size_t)(col0 + row) * K + k0 + c8);
        }
    };

#pragma unroll
    for (int s = 0; s < NST - 1; s++) {
        if (s < nch) load_chunk(s, s);
        cp_commit();
    }

    int stg = 0;
    for (int c = 0; c < nch; c++) {
        cp_wait<NST - 2>();
        __syncthreads();
        int pf = c + NST - 1;
        int pstg = stg + NST - 1; if (pstg >= NST) pstg -= NST;
        if (pf < nch) load_chunk(pf, pstg);
        cp_commit();

        uint32_t base = sbase + (uint32_t)stg * STAGEB;
#pragma unroll
        for (int s = 0; s < 4; s++) {
            uint32_t scol = (uint32_t)(s * 32);
            uint32_t ah[2][4], bf[4][4];
#pragma unroll
            for (int mi = 0; mi < 2; mi++) {
                uint32_t ao = base + a_off + scol + (uint32_t)(mi * 16 * SSTR * 2);
                ldsm_x4(ah[mi], ao);
            }
#pragma unroll
            for (int nj = 0; nj < 4; nj++) {
                uint32_t bo = base + TILEB + b_off + scol + (uint32_t)(nj * 16 * SSTR * 2);
                ldsm_x4(bf[nj], bo);
            }
#pragma unroll
            for (int mi = 0; mi < 2; mi++)
#pragma unroll
                for (int nj = 0; nj < 4; nj++) {
                    mma_f16(acc[mi][2*nj + 0], ah[mi], &bf[nj][0]);
                    mma_f16(acc[mi][2*nj + 1], ah[mi], &bf[nj][2]);
                }
        }
        if (++stg == NST) stg = 0;
    }

    int gid = lane >> 2, qid = lane & 3;
#pragma unroll
    for (int mi = 0; mi < 2; mi++) {
#pragma unroll
        for (int nj = 0; nj < 8; nj++) {
            int col = col0 + wc * 64 + nj * 8 + qid * 2;
            float b0 = bias[col], b1 = bias[col + 1];
#pragma unroll
            for (int half = 0; half < 2; half++) {
                int row = row0 + wr * 32 + mi * 16 + gid + half * 8;
                float v0 = acc[mi][nj][half * 2 + 0] + b0;
                float v1 = acc[mi][nj][half * 2 + 1] + b1;
                if (relu) { v0 = fmaxf(v0, 0.f); v1 = fmaxf(v1, 0.f); }
                size_t off = (size_t)row * N + col;
                if (wf32) {
                    if (Res) {
                        float2 r = *(const float2*)(Res + off);
                        v0 += r.x; v1 += r.y;
                    }
                    *(float2*)(C + off) = make_float2(v0, v1);
                }
                if (wbf) {
                    uint32_t hp = pack_hf(v0, v1);
                    *(uint32_t*)(Ch + off) = hp;
                }
            }
        }
    }
}

// ---------------- head with fused final LayerNorm (warp per row) ----------------
__global__ void __launch_bounds__(256) head_kernel(
    const float* __restrict__ x, const float* __restrict__ fg,
    const float* __restrict__ fb, const float* __restrict__ W,
    const float* __restrict__ b, float* __restrict__ out)
{
    int warp = threadIdx.x >> 5;
    int lane = threadIdx.x & 31;
    int row = blockIdx.x * 8 + warp;
    if (row >= MTOT) return;

    const float4* xr = (const float4*)(x + (size_t)row * DD);
    float4 xv[4];
    float s = 0.f;
#pragma unroll
    for (int k = 0; k < 4; k++) {
        xv[k] = xr[lane + 32 * k];
        s += xv[k].x + xv[k].y + xv[k].z + xv[k].w;
    }
#pragma unroll
    for (int o = 16; o > 0; o >>= 1) s += __shfl_xor_sync(0xffffffffu, s, o);
    float mu = s * (1.f / DD);
    float q2 = 0.f;
#pragma unroll
    for (int k = 0; k < 4; k++) {
        xv[k].x -= mu; xv[k].y -= mu; xv[k].z -= mu; xv[k].w -= mu;
        q2 += xv[k].x*xv[k].x + xv[k].y*xv[k].y + xv[k].z*xv[k].z + xv[k].w*xv[k].w;
    }
#pragma unroll
    for (int o = 16; o > 0; o >>= 1) q2 += __shfl_xor_sync(0xffffffffu, q2, o);
    float rs = rsqrtf(q2 * (1.f / DD) + 1e-5f);
#pragma unroll
    for (int k = 0; k < 4; k++) {
        float4 gv = ((const float4*)fg)[lane + 32 * k];
        float4 bv = ((const float4*)fb)[lane + 32 * k];
        xv[k].x = xv[k].x * rs * gv.x + bv.x;
        xv[k].y = xv[k].y * rs * gv.y + bv.y;
        xv[k].z = xv[k].z * rs * gv.z + bv.z;
        xv[k].w = xv[k].w * rs * gv.w + bv.w;
    }

    float sums[CC];
#pragma unroll
    for (int c = 0; c < CC; c++) {
        const float4* wr = (const float4*)(W + (size_t)c * DD);
        float sv = 0.f;
#pragma unroll
        for (int k = 0; k < 4; k++) {
            float4 wv = wr[lane + 32 * k];
            sv += xv[k].x * wv.x + xv[k].y * wv.y + xv[k].z * wv.z + xv[k].w * wv.w;
        }
#pragma unroll
        for (int o = 16; o > 0; o >>= 1) sv += __shfl_xor_sync(0xffffffffu, sv, o);
        sums[c] = sv;
    }
    if (lane == 0) {
#pragma unroll
        for (int c = 0; c < CC; c++) out[(size_t)row * CC + c] = sums[c] + b[c];
    }
}

// ================== tensor-core flash attention (fp16 MMA) ==================
// CTA = 64 queries of one (b,h), 128 threads (4 warps),
// double-buffered 64-key K/V tiles via cp.async.
#define QSTR 72

__global__ void __launch_bounds__(128) attn_mma(
    const __half* __restrict__ Q, const __half* __restrict__ K,
    const __half* __restrict__ V, const unsigned char* __restrict__ kpm,
    __half* __restrict__ Oh, int ldq)
{
    __shared__ __half Qs[64][QSTR];
    __shared__ __half Ks[2][64][QSTR];
    __shared__ __half Vs[2][64][QSTR];
    __shared__ unsigned char Ms[2][64];

    int b = blockIdx.z, h = blockIdx.y, q0 = blockIdx.x << 6;
    int tid = threadIdx.x;
    int w    = tid >> 5;
    int lane = tid & 31;
    int g    = lane >> 3;
    int lr   = lane & 7;
    int gid  = lane >> 2;
    int q2   = lane & 3;

    uint32_t qs_b  = smem_u32(&Qs[0][0]);
    uint32_t ks_b0 = smem_u32(&Ks[0][0][0]);
    uint32_t vs_b0 = smem_u32(&Vs[0][0][0]);
    const uint32_t KVBUF = (uint32_t)(64 * QSTR * 2);

    auto load_kv = [&](int kt, int bb) {
#pragma unroll
        for (int t = 0; t < 4; t++) {
            int i = tid + 128 * t;
            int row = i >> 3;
            int c8  = (i & 7) << 3;
            size_t gsrc = (size_t)(b * NN + kt * 64 + row) * ldq + h * HD + c8;
            uint32_t doff = (uint32_t)((row * QSTR + c8) * 2);
            cpa16(ks_b0 + bb * KVBUF + doff, K + gsrc);
            cpa16(vs_b0 + bb * KVBUF + doff, V + gsrc);
        }
        if (tid < 4)
            cpa16(smem_u32(&Ms[bb][0]) + tid * 16, kpm + b * NN + kt * 64 + tid * 16);
    };

#pragma unroll
    for (int t = 0; t < 4; t++) {
        int i = tid + 128 * t;
        int row = i >> 3;
        int c8  = (i & 7) << 3;
        cpa16(qs_b + (uint32_t)((row * QSTR + c8) * 2),
              Q + (size_t)(b * NN + q0 + row) * ldq + h * HD + c8);
    }
    load_kv(0, 0);
    cp_commit();
    load_kv(1, 1);
    cp_commit();

    float oacc[8][4];
#pragma unroll
    for (int nj = 0; nj < 8; nj++)
#pragma unroll
        for (int u = 0; u < 4; u++) oacc[nj][u] = 0.f;
    float m0 = -1e30f, m1 = -1e30f, l0 = 0.f, l1 = 0.f;

    uint32_t a_off = (uint32_t)(((16 * w + (g & 1) * 8 + lr) * QSTR + (g >> 1) * 8) * 2);

    for (int kt = 0; kt < NN / 64; kt++) {
        cp_wait<1>();
        __syncthreads();
        int bb = kt & 1;
        uint32_t ks_b = ks_b0 + bb * KVBUF;
        uint32_t vs_b = vs_b0 + bb * KVBUF;

        float sacc[8][4];
#pragma unroll
        for (int nj = 0; nj < 8; nj++)
#pragma unroll
            for (int u = 0; u < 4; u++) sacc[nj][u] = 0.f;
#pragma unroll
        for (int s = 0; s < 4; s++) {
            uint32_t aq[4];
            ldsm_x4(aq, qs_b + a_off + (uint32_t)(s * 32));
#pragma unroll
            for (int nt = 0; nt < 4; nt++) {
                uint32_t bk[4];
                ldsm_x4(bk, ks_b + (uint32_t)(((nt * 16 + (g >> 1) * 8 + lr) * QSTR
                                               + (g & 1) * 8 + s * 16) * 2));
                mma_f16(sacc[2*nt + 0], aq, &bk[0]);
                mma_f16(sacc[2*nt + 1], aq, &bk[2]);
            }
        }

        float mx0 = -1e30f, mx1 = -1e30f;
#pragma unroll
        for (int nj = 0; nj < 8; nj++) {
            int kc = nj * 8 + 2 * q2;
            bool msk0 = Ms[bb][kc] != 0;
            bool msk1 = Ms[bb][kc + 1] != 0;
            sacc[nj][0] = msk0 ? -1e30f : sacc[nj][0] * 0.125f;
            sacc[nj][1] = msk1 ? -1e30f : sacc[nj][1] * 0.125f;
            sacc[nj][2] = msk0 ? -1e30f : sacc[nj][2] * 0.125f;
            sacc[nj][3] = msk1 ? -1e30f : sacc[nj][3] * 0.125f;
            mx0 = fmaxf(mx0, fmaxf(sacc[nj][0], sacc[nj][1]));
            mx1 = fmaxf(mx1, fmaxf(sacc[nj][2], sacc[nj][3]));
        }
        mx0 = fmaxf(mx0, __shfl_xor_sync(0xffffffffu, mx0, 1));
        mx0 = fmaxf(mx0, __shfl_xor_sync(0xffffffffu, mx0, 2));
        mx1 = fmaxf(mx1, __shfl_xor_sync(0xffffffffu, mx1, 1));
        mx1 = fmaxf(mx1, __shfl_xor_sync(0xffffffffu, mx1, 2));
        float mn0 = fmaxf(m0, mx0), mn1 = fmaxf(m1, mx1);
        float cr0 = __expf(m0 - mn0), cr1 = __expf(m1 - mn1);

        float s0 = 0.f, s1 = 0.f;
#pragma unroll
        for (int nj = 0; nj < 8; nj++) {
            sacc[nj][0] = __expf(sacc[nj][0] - mn0);
            sacc[nj][1] = __expf(sacc[nj][1] - mn0);
            sacc[nj][2] = __expf(sacc[nj][2] - mn1);
            sacc[nj][3] = __expf(sacc[nj][3] - mn1);
            s0 += sacc[nj][0] + sacc[nj][1];
            s1 += sacc[nj][2] + sacc[nj][3];
        }
        s0 += __shfl_xor_sync(0xffffffffu, s0, 1);
        s0 += __shfl_xor_sync(0xffffffffu, s0, 2);
        s1 += __shfl_xor_sync(0xffffffffu, s1, 1);
        s1 += __shfl_xor_sync(0xffffffffu, s1, 2);
        l0 = l0 * cr0 + s0;
        l1 = l1 * cr1 + s1;
        m0 = mn0; m1 = mn1;
#pragma unroll
        for (int nj = 0; nj < 8; nj++) {
            oacc[nj][0] *= cr0; oacc[nj][1] *= cr0;
            oacc[nj][2] *= cr1; oacc[nj][3] *= cr1;
        }

#pragma unroll
        for (int s = 0; s < 4; s++) {
            uint32_t pa[4];
            pa[0] = pack_hf(sacc[2*s][0],   sacc[2*s][1]);
            pa[1] = pack_hf(sacc[2*s][2],   sacc[2*s][3]);
            pa[2] = pack_hf(sacc[2*s+1][0], sacc[2*s+1][1]);
            pa[3] = pack_hf(sacc[2*s+1][2], sacc[2*s+1][3]);
#pragma unroll
            for (int t = 0; t < 4; t++) {
                uint32_t bv[4];
                ldsm_x4_t(bv, vs_b + (uint32_t)(((16 * s + (g & 1) * 8 + lr) * QSTR
                                                 + 8 * (2 * t + (g >> 1))) * 2));
                mma_f16(oacc[2*t + 0], pa, &bv[0]);
                mma_f16(oacc[2*t + 1], pa, &bv[2]);
            }
        }

        __syncthreads();
        if (kt + 2 < NN / 64) {
            load_kv(kt + 2, bb);
        }
        cp_commit();
    }

    float inv0 = (l0 > 0.f) ? (1.f / l0) : 0.f;
    float inv1 = (l1 > 0.f) ? (1.f / l1) : 0.f;
    size_t r0g = (size_t)(b * NN + q0 + 16 * w + gid) * DD + h * HD;
    size_t r1g = r0g + (size_t)8 * DD;
#pragma unroll
    for (int nj = 0; nj < 8; nj++) {
        int col = nj * 8 + 2 * q2;
        *(uint32_t*)(Oh + r0g + col) = pack_hf(oacc[nj][0] * inv0, oacc[nj][1] * inv0);
        *(uint32_t*)(Oh + r1g + col) = pack_hf(oacc[nj][2] * inv1, oacc[nj][3] * inv1);
    }
}

// ---------------- LayerNorm (warp per row, no barriers, single input) ----------------
__global__ void __launch_bounds__(256) ln_kernel(
    const float* __restrict__ x,
    const float* __restrict__ g, const float* __restrict__ bparam,
    float* __restrict__ out,
    __half* __restrict__ outh)
{
    int warp = threadIdx.x >> 5;
    int lane = threadIdx.x & 31;
    int row = blockIdx.x * 8 + warp;
    if (row >= MTOT) return;

    const float4* xr = (const float4*)(x + (size_t)row * DD);
    float4 v[4];
    float s = 0.f;
#pragma unroll
    for (int k = 0; k < 4; k++) {
        v[k] = xr[lane + 32 * k];
        s += v[k].x + v[k].y + v[k].z + v[k].w;
    }
#pragma unroll
    for (int o = 16; o > 0; o >>= 1) s += __shfl_xor_sync(0xffffffffu, s, o);
    float mu = s * (1.f / DD);
    float q2 = 0.f;
#pragma unroll
    for (int k = 0; k < 4; k++) {
        v[k].x -= mu; v[k].y -= mu; v[k].z -= mu; v[k].w -= mu;
        q2 += v[k].x*v[k].x + v[k].y*v[k].y + v[k].z*v[k].z + v[k].w*v[k].w;
    }
#pragma unroll
    for (int o = 16; o > 0; o >>= 1) q2 += __shfl_xor_sync(0xffffffffu, q2, o);
    float rs = rsqrtf(q2 * (1.f / DD) + 1e-5f);

    float4* outr = (float4*)(out + (size_t)row * DD);
    uint2* outhr = (uint2*)(outh + (size_t)row * DD);
#pragma unroll
    for (int k = 0; k < 4; k++) {
        float4 gv = ((const float4*)g)[lane + 32 * k];
        float4 bv = ((const float4*)bparam)[lane + 32 * k];
        float4 o;
        o.x = v[k].x * rs * gv.x + bv.x;
        o.y = v[k].y * rs * gv.y + bv.y;
        o.z = v[k].z * rs * gv.z + bv.z;
        o.w = v[k].w * rs * gv.w + bv.w;
        outr[lane + 32 * k] = o;
        uint2 hp;
        hp.x = pack_hf(o.x, o.y);
        hp.y = pack_hf(o.z, o.w);
        outhr[lane + 32 * k] = hp;
    }
}

// ---------------- launch ----------------
extern "C" void kernel_launch(void* const* d_in, const int* in_sizes, int n_in,
                              void* d_out, int out_size)
{
    const float* src      = (const float*)d_in[0];
    const unsigned char* kpm = (const unsigned char*)d_in[1];
    const float* embed_W  = (const float*)d_in[2];
    const float* embed_b  = (const float*)d_in[3];
    const float* Wq = (const float*)d_in[4];
    const float* bq = (const float*)d_in[5];
    const float* Wk = (const float*)d_in[6];
    const float* bk = (const float*)d_in[7];
    const float* Wv = (const float*)d_in[8];
    const float* bv = (const float*)d_in[9];
    const float* Wo = (const float*)d_in[10];
    const float* bo = (const float*)d_in[11];
    const float* W1 = (const float*)d_in[12];
    const float* b1 = (const float*)d_in[13];
    const float* W2 = (const float*)d_in[14];
    const float* b2 = (const float*)d_in[15];
    const float* ln1_g = (const float*)d_in[16];
    const float* ln1_b = (const float*)d_in[17];
    const float* ln2_g = (const float*)d_in[18];
    const float* ln2_b = (const float*)d_in[19];
    const float* fin_g = (const float*)d_in[20];
    const float* fin_b = (const float*)d_in[21];
    const float* head_W = (const float*)d_in[22];
    const float* head_b = (const float*)d_in[23];

    float *x, *q, *t;
    cudaGetSymbolAddress((void**)&x, g_x);
    cudaGetSymbolAddress((void**)&q, g_q);
    cudaGetSymbolAddress((void**)&t, g_t);

    __half *qkv, *xh, *th, *ffh, *shp;
    __half *wqkvh, *woh, *w1h, *w2h, *ewh;
    float *bqkv;
    cudaGetSymbolAddress((void**)&qkv, g_qkv);
    cudaGetSymbolAddress((void**)&xh, g_xh);
    cudaGetSymbolAddress((void**)&th, g_th);
    cudaGetSymbolAddress((void**)&ffh, g_ffh);
    cudaGetSymbolAddress((void**)&shp, g_sh);
    cudaGetSymbolAddress((void**)&wqkvh, g_wqkvh);
    cudaGetSymbolAddress((void**)&bqkv, g_bqkv);
    cudaGetSymbolAddress((void**)&woh, g_woh);
    cudaGetSymbolAddress((void**)&w1h, g_w1h);
    cudaGetSymbolAddress((void**)&w2h, g_w2h);
    cudaGetSymbolAddress((void**)&ewh, g_ewh);

    cudaFuncSetAttribute(gemm_hf, cudaFuncAttributeMaxDynamicSharedMemorySize, GB_SMEM);

    const int TS = 256;
    auto blocks = [](size_t n4) { return (int)((n4 + 255) / 256); };
    size_t nQKV = (size_t)LL * 3 * DD * DD / 4;

    int nWo = (int)((size_t)LL * DD * DD / 4);      // 393216
    int nW1 = (int)((size_t)LL * FFD * DD / 4);     // 1572864
    int nW2 = nW1;
    int nEw = DD * DIN / 4;                          // 8192
    int nSrc = MTOT * DIN / 4;                       // 131072
    size_t nMulti = (size_t)nWo + nW1 + nW2 + nEw + nSrc;

    conv_qkv<<<blocks(nQKV), TS>>>(Wq, Wk, Wv, wqkvh, (int)nQKV);
    concat_bias<<<(LL*QKVD + 255)/256, TS>>>(bq, bk, bv, bqkv);
    conv_multi<<<blocks(nMulti), TS>>>(Wo, woh, nWo,
                                       W1, w1h, nW1,
                                       W2, w2h, nW2,
                                       embed_W, ewh, nEw,
                                       src, shp, nSrc);

    dim3 gD(DD/128, MTOT/128);       // 4 x 64
    dim3 gQKV(QKVD/128, MTOT/128);   // 12 x 64
    dim3 gF(FFD/128, MTOT/128);      // 16 x 64
    dim3 gA(NN/64, HH, BB);          // 16 x 8 x 8

    gemm_hf<<<gD, 256, GB_SMEM>>>(MTOT, DD, DIN, shp, ewh,
                                  embed_b, nullptr, x, xh, 0, 1, 1);

    for (int l = 0; l < LL; l++) {
        size_t offW = (size_t)l * DD * DD;
        size_t offQKV = (size_t)l * QKVD * DD;
        size_t offF = (size_t)l * FFD * DD;

        // fused QKV GEMM -> packed fp16 [M, 1536]
        gemm_hf<<<gQKV, 256, GB_SMEM>>>(MTOT, QKVD, DD, xh,
                                        wqkvh + offQKV,
                                        bqkv + l*QKVD, nullptr, nullptr, qkv, 0, 0, 1);

        attn_mma<<<gA, 128>>>(qkv, qkv + DD, qkv + 2*DD, kpm, th, QKVD);

        // Wo-proj with fused residual: q = attn_proj + x
        gemm_hf<<<gD, 256, GB_SMEM>>>(MTOT, DD, DD, th, woh + offW,
                                      bo + l*DD, x, q, nullptr, 0, 1, 0);
        ln_kernel<<<MTOT/8, 256>>>(q, ln1_g + l*DD, ln1_b + l*DD, x, xh);

        gemm_hf<<<gF, 256, GB_SMEM>>>(MTOT, FFD, DD, xh, w1h + offF,
                                      b1 + l*FFD, nullptr, nullptr, ffh, 1, 0, 1);
        // FF2 with fused residual: t = ff2 + x
        gemm_hf<<<gD, 256, GB_SMEM>>>(MTOT, DD, FFD, ffh, w2h + offF,
                                      b2 + l*DD, x, t, nullptr, 0, 1, 0);
        ln_kernel<<<MTOT/8, 256>>>(t, ln2_g + l*DD, ln2_b + l*DD, x, xh);
    }

    head_kernel<<<MTOT/8, 256>>>(x, fin_g, fin_b, head_W, head_b, (float*)d_out);
}

// round 16
// speedup vs baseline: 1.0156x; 1.0156x over previous
#include <cuda_runtime.h>
#include <cuda_fp16.h>
#include <cstdint>
#include <cstddef>

// Problem constants
#define BB    8
#define NN    1024
#define DD    512
#define HH    8
#define HD    64
#define FFD   2048
#define LL    6
#define CC    5
#define DIN   64
#define MTOT  (BB*NN)   // 8192
#define QKVD  (3*DD)    // 1536

// ---------------- static scratch (no allocations allowed) ----------------
__device__ float g_x [MTOT*DD];
__device__ float g_q [MTOT*DD];     // attn out-proj result (fp32, pre-LN)
__device__ float g_t [MTOT*DD];     // FF2 result (fp32, pre-LN)

// fp16 buffers
__device__ __half g_qkv[(size_t)MTOT*QKVD];
__device__ __half g_xh [MTOT*DD];
__device__ __half g_th [MTOT*DD];
__device__ __half g_ffh[(size_t)MTOT*FFD];
__device__ __half g_sh [MTOT*DIN];
__device__ __half g_wqkvh[(size_t)LL*QKVD*DD];
__device__ float  g_bqkv [LL*QKVD];
__device__ __half g_woh[LL*DD*DD];
__device__ __half g_w1h[(size_t)LL*FFD*DD];
__device__ __half g_w2h[(size_t)LL*DD*FFD];
__device__ __half g_ewh[DD*DIN];

// ================= helpers =================
__device__ __forceinline__ uint32_t smem_u32(const void* p) {
    uint32_t a;
    asm("{ .reg .u64 t; cvta.to.shared.u64 t, %1; cvt.u32.u64 %0, t; }" : "=r"(a) : "l"(p));
    return a;
}
__device__ __forceinline__ void ldsm_x4(uint32_t* r, uint32_t addr) {
    asm volatile("ldmatrix.sync.aligned.m8n8.x4.shared.b16 {%0,%1,%2,%3}, [%4];"
                 : "=r"(r[0]), "=r"(r[1]), "=r"(r[2]), "=r"(r[3]) : "r"(addr));
}
__device__ __forceinline__ void ldsm_x4_t(uint32_t* r, uint32_t addr) {
    asm volatile("ldmatrix.sync.aligned.m8n8.x4.trans.shared.b16 {%0,%1,%2,%3}, [%4];"
                 : "=r"(r[0]), "=r"(r[1]), "=r"(r[2]), "=r"(r[3]) : "r"(addr));
}
__device__ __forceinline__ void mma_f16(float* d, const uint32_t* a, const uint32_t* b) {
    asm volatile(
        "mma.sync.aligned.m16n8k16.row.col.f32.f16.f16.f32 "
        "{%0,%1,%2,%3}, {%4,%5,%6,%7}, {%8,%9}, {%0,%1,%2,%3};"
        : "+f"(d[0]), "+f"(d[1]), "+f"(d[2]), "+f"(d[3])
        : "r"(a[0]), "r"(a[1]), "r"(a[2]), "r"(a[3]), "r"(b[0]), "r"(b[1]));
}
__device__ __forceinline__ void cpa16(uint32_t dst, const void* src) {
    asm volatile("cp.async.ca.shared.global [%0], [%1], 16;"
                 :: "r"(dst), "l"(__cvta_generic_to_global(src)));
}
__device__ __forceinline__ void cp_commit() {
    asm volatile("cp.async.commit_group;");
}
template<int N> __device__ __forceinline__ void cp_wait() {
    asm volatile("cp.async.wait_group %0;" :: "n"(N));
}
__device__ __forceinline__ uint32_t pack_hf(float a, float b) {
    __half2 p = __floats2half2_rn(a, b);
    return *(uint32_t*)&p;
}

// ---------------- merged fp32 -> fp16 conversion (5 segments in one launch) ----
__global__ void __launch_bounds__(256) conv_multi(
    const float* __restrict__ i0, __half* __restrict__ o0, int n0,
    const float* __restrict__ i1, __half* __restrict__ o1, int n1,
    const float* __restrict__ i2, __half* __restrict__ o2, int n2,
    const float* __restrict__ i3, __half* __restrict__ o3, int n3,
    const float* __restrict__ i4, __half* __restrict__ o4, int n4)
{
    int i = blockIdx.x * blockDim.x + threadIdx.x;
    const float* in; __half* out; int idx;
    if (i < n0)                    { in = i0; out = o0; idx = i; }
    else if ((i -= n0) < n1)       { in = i1; out = o1; idx = i; }
    else if ((i -= n1) < n2)       { in = i2; out = o2; idx = i; }
    else if ((i -= n2) < n3)       { in = i3; out = o3; idx = i; }
    else if ((i -= n3) < n4)       { in = i4; out = o4; idx = i; }
    else return;
    float4 v = ((const float4*)in)[idx];
    uint2 hv;
    hv.x = pack_hf(v.x, v.y);
    hv.y = pack_hf(v.z, v.w);
    ((uint2*)out)[idx] = hv;
}

// ---------------- fused QKV weight convert: [L][3][D][D] from Wq/Wk/Wv ----
__global__ void __launch_bounds__(256) conv_qkv(
    const float* __restrict__ Wq, const float* __restrict__ Wk,
    const float* __restrict__ Wv, __half* __restrict__ out, int n4)
{
    int i = blockIdx.x * blockDim.x + threadIdx.x;
    if (i >= n4) return;
    const int per_mat = DD * DD / 4;
    int l = i / (3 * per_mat);
    int rem = i - l * (3 * per_mat);
    int which = rem / per_mat;
    int r2 = rem - which * per_mat;
    const float* src = (which == 0 ? Wq : (which == 1 ? Wk : Wv)) + (size_t)l * DD * DD;
    float4 v = ((const float4*)src)[r2];
    uint2 hv;
    hv.x = pack_hf(v.x, v.y);
    hv.y = pack_hf(v.z, v.w);
    ((uint2*)out)[i] = hv;
}

// ---------------- concat qkv biases ----------------
__global__ void __launch_bounds__(256) concat_bias(
    const float* __restrict__ bq, const float* __restrict__ bk,
    const float* __restrict__ bv, float* __restrict__ out)
{
    int idx = blockIdx.x * blockDim.x + threadIdx.x;
    if (idx >= LL * QKVD) return;
    int l = idx / QKVD, r = idx % QKVD;
    float v = (r < DD) ? bq[l * DD + r]
            : (r < 2 * DD) ? bk[l * DD + r - DD]
            : bv[l * DD + r - 2 * DD];
    out[idx] = v;
}

// ================== pipelined plain-fp16 GEMM ==================
// BM=128 BN=128 BK=64, 256 threads = 8 warps (4m x 2n), warp tile 32x64.
// 3-stage cp.async pipeline, 108KB SMEM -> 2 CTAs/SM.
#define SSTR    72
#define TILEB   (128*SSTR*2)       // 18432 B
#define STAGEB  (2*TILEB)          // 36864 B
#define NST     3
#define GB_SMEM (NST*STAGEB)       // 110592 B

__global__ void __launch_bounds__(256, 2) gemm_hf(
    int M, int N, int K,
    const __half* __restrict__ Ah,
    const __half* __restrict__ Bh,
    const float* __restrict__ bias,
    float* __restrict__ C,
    __half* __restrict__ Ch,
    int relu, int wf32, int wbf)
{
    extern __shared__ char smem[];
    uint32_t sbase = smem_u32(smem);

    int tid  = threadIdx.x;
    int lane = tid & 31;
    int wid  = tid >> 5;
    int wr   = wid >> 1;
    int wc   = wid & 1;
    int g    = lane >> 3;
    int lr   = lane & 7;

    int row0 = blockIdx.y << 7;
    int col0 = blockIdx.x << 7;

    float acc[2][8][4];
#pragma unroll
    for (int mi = 0; mi < 2; mi++)
#pragma unroll
        for (int ni = 0; ni < 8; ni++)
#pragma unroll
            for (int u = 0; u < 4; u++) acc[mi][ni][u] = 0.f;

    uint32_t a_off = (uint32_t)(((wr * 32 + (g & 1) * 8 + lr) * SSTR + (g >> 1) * 8) * 2);
    uint32_t b_off = (uint32_t)(((wc * 64 + (g >> 1) * 8 + lr) * SSTR + (g & 1) * 8) * 2);

    const int nch = K >> 6;

    auto load_chunk = [&](int c, int stg) {
        uint32_t sb = sbase + (uint32_t)stg * STAGEB;
        int k0 = c << 6;
#pragma unroll
        for (int t = 0; t < 4; t++) {
            int i = tid + 256 * t;
            int row = i >> 3;
            int c8  = (i & 7) << 3;
            uint32_t doff = (uint32_t)((row * SSTR + c8) * 2);
            cpa16(sb + doff,         Ah + (size_t)(row0 + row) * K + k0 + c8);
            cpa16(sb + TILEB + doff, Bh + (size_t)(col0 + row) * K + k0 + c8);
        }
    };

#pragma unroll
    for (int s = 0; s < NST - 1; s++) {
        if (s < nch) load_chunk(s, s);
        cp_commit();
    }

    int stg = 0;
    for (int c = 0; c < nch; c++) {
        cp_wait<NST - 2>();
        __syncthreads();
        int pf = c + NST - 1;
        int pstg = stg + NST - 1; if (pstg >= NST) pstg -= NST;
        if (pf < nch) load_chunk(pf, pstg);
        cp_commit();

        uint32_t base = sbase + (uint32_t)stg * STAGEB;
#pragma unroll
        for (int s = 0; s < 4; s++) {
            uint32_t scol = (uint32_t)(s * 32);
            uint32_t ah[2][4], bf[4][4];
#pragma unroll
            for (int mi = 0; mi < 2; mi++) {
                uint32_t ao = base + a_off + scol + (uint32_t)(mi * 16 * SSTR * 2);
                ldsm_x4(ah[mi], ao);
            }
#pragma unroll
            for (int nj = 0; nj < 4; nj++) {
                uint32_t bo = base + TILEB + b_off + scol + (uint32_t)(nj * 16 * SSTR * 2);
                ldsm_x4(bf[nj], bo);
            }
#pragma unroll
            for (int mi = 0; mi < 2; mi++)
#pragma unroll
                for (int nj = 0; nj < 4; nj++) {
                    mma_f16(acc[mi][2*nj + 0], ah[mi], &bf[nj][0]);
                    mma_f16(acc[mi][2*nj + 1], ah[mi], &bf[nj][2]);
                }
        }
        if (++stg == NST) stg = 0;
    }

    int gid = lane >> 2, qid = lane & 3;
#pragma unroll
    for (int mi = 0; mi < 2; mi++) {
#pragma unroll
        for (int nj = 0; nj < 8; nj++) {
            int col = col0 + wc * 64 + nj * 8 + qid * 2;
            float b0 = bias[col], b1 = bias[col + 1];
#pragma unroll
            for (int half = 0; half < 2; half++) {
                int row = row0 + wr * 32 + mi * 16 + gid + half * 8;
                float v0 = acc[mi][nj][half * 2 + 0] + b0;
                float v1 = acc[mi][nj][half * 2 + 1] + b1;
                if (relu) { v0 = fmaxf(v0, 0.f); v1 = fmaxf(v1, 0.f); }
                size_t off = (size_t)row * N + col;
                if (wf32) *(float2*)(C + off) = make_float2(v0, v1);
                if (wbf) {
                    uint32_t hp = pack_hf(v0, v1);
                    *(uint32_t*)(Ch + off) = hp;
                }
            }
        }
    }
}

// ---------------- head with fused final LayerNorm (warp per row) ----------------
__global__ void __launch_bounds__(256) head_kernel(
    const float* __restrict__ x, const float* __restrict__ fg,
    const float* __restrict__ fb, const float* __restrict__ W,
    const float* __restrict__ b, float* __restrict__ out)
{
    int warp = threadIdx.x >> 5;
    int lane = threadIdx.x & 31;
    int row = blockIdx.x * 8 + warp;
    if (row >= MTOT) return;

    const float4* xr = (const float4*)(x + (size_t)row * DD);
    float4 xv[4];
    float s = 0.f;
#pragma unroll
    for (int k = 0; k < 4; k++) {
        xv[k] = xr[lane + 32 * k];
        s += xv[k].x + xv[k].y + xv[k].z + xv[k].w;
    }
#pragma unroll
    for (int o = 16; o > 0; o >>= 1) s += __shfl_xor_sync(0xffffffffu, s, o);
    float mu = s * (1.f / DD);
    float q2 = 0.f;
#pragma unroll
    for (int k = 0; k < 4; k++) {
        xv[k].x -= mu; xv[k].y -= mu; xv[k].z -= mu; xv[k].w -= mu;
        q2 += xv[k].x*xv[k].x + xv[k].y*xv[k].y + xv[k].z*xv[k].z + xv[k].w*xv[k].w;
    }
#pragma unroll
    for (int o = 16; o > 0; o >>= 1) q2 += __shfl_xor_sync(0xffffffffu, q2, o);
    float rs = rsqrtf(q2 * (1.f / DD) + 1e-5f);
#pragma unroll
    for (int k = 0; k < 4; k++) {
        float4 gv = ((const float4*)fg)[lane + 32 * k];
        float4 bv = ((const float4*)fb)[lane + 32 * k];
        xv[k].x = xv[k].x * rs * gv.x + bv.x;
        xv[k].y = xv[k].y * rs * gv.y + bv.y;
        xv[k].z = xv[k].z * rs * gv.z + bv.z;
        xv[k].w = xv[k].w * rs * gv.w + bv.w;
    }

    float sums[CC];
#pragma unroll
    for (int c = 0; c < CC; c++) {
        const float4* wr = (const float4*)(W + (size_t)c * DD);
        float sv = 0.f;
#pragma unroll
        for (int k = 0; k < 4; k++) {
            float4 wv = wr[lane + 32 * k];
            sv += xv[k].x * wv.x + xv[k].y * wv.y + xv[k].z * wv.z + xv[k].w * wv.w;
        }
#pragma unroll
        for (int o = 16; o > 0; o >>= 1) sv += __shfl_xor_sync(0xffffffffu, sv, o);
        sums[c] = sv;
    }
    if (lane == 0) {
#pragma unroll
        for (int c = 0; c < CC; c++) out[(size_t)row * CC + c] = sums[c] + b[c];
    }
}

// ================== tensor-core flash attention (fp16 MMA) ==================
// CTA = 64 queries of one (b,h), 128 threads (4 warps),
// double-buffered 64-key K/V tiles via cp.async.
#define QSTR 72

__global__ void __launch_bounds__(128) attn_mma(
    const __half* __restrict__ Q, const __half* __restrict__ K,
    const __half* __restrict__ V, const unsigned char* __restrict__ kpm,
    __half* __restrict__ Oh, int ldq)
{
    __shared__ __half Qs[64][QSTR];
    __shared__ __half Ks[2][64][QSTR];
    __shared__ __half Vs[2][64][QSTR];
    __shared__ unsigned char Ms[2][64];

    int b = blockIdx.z, h = blockIdx.y, q0 = blockIdx.x << 6;
    int tid = threadIdx.x;
    int w    = tid >> 5;
    int lane = tid & 31;
    int g    = lane >> 3;
    int lr   = lane & 7;
    int gid  = lane >> 2;
    int q2   = lane & 3;

    uint32_t qs_b  = smem_u32(&Qs[0][0]);
    uint32_t ks_b0 = smem_u32(&Ks[0][0][0]);
    uint32_t vs_b0 = smem_u32(&Vs[0][0][0]);
    const uint32_t KVBUF = (uint32_t)(64 * QSTR * 2);

    auto load_kv = [&](int kt, int bb) {
#pragma unroll
        for (int t = 0; t < 4; t++) {
            int i = tid + 128 * t;
            int row = i >> 3;
            int c8  = (i & 7) << 3;
            size_t gsrc = (size_t)(b * NN + kt * 64 + row) * ldq + h * HD + c8;
            uint32_t doff = (uint32_t)((row * QSTR + c8) * 2);
            cpa16(ks_b0 + bb * KVBUF + doff, K + gsrc);
            cpa16(vs_b0 + bb * KVBUF + doff, V + gsrc);
        }
        if (tid < 4)
            cpa16(smem_u32(&Ms[bb][0]) + tid * 16, kpm + b * NN + kt * 64 + tid * 16);
    };

#pragma unroll
    for (int t = 0; t < 4; t++) {
        int i = tid + 128 * t;
        int row = i >> 3;
        int c8  = (i & 7) << 3;
        cpa16(qs_b + (uint32_t)((row * QSTR + c8) * 2),
              Q + (size_t)(b * NN + q0 + row) * ldq + h * HD + c8);
    }
    load_kv(0, 0);
    cp_commit();
    load_kv(1, 1);
    cp_commit();

    float oacc[8][4];
#pragma unroll
    for (int nj = 0; nj < 8; nj++)
#pragma unroll
        for (int u = 0; u < 4; u++) oacc[nj][u] = 0.f;
    float m0 = -1e30f, m1 = -1e30f, l0 = 0.f, l1 = 0.f;

    uint32_t a_off = (uint32_t)(((16 * w + (g & 1) * 8 + lr) * QSTR + (g >> 1) * 8) * 2);

    for (int kt = 0; kt < NN / 64; kt++) {
        cp_wait<1>();
        __syncthreads();
        int bb = kt & 1;
        uint32_t ks_b = ks_b0 + bb * KVBUF;
        uint32_t vs_b = vs_b0 + bb * KVBUF;

        float sacc[8][4];
#pragma unroll
        for (int nj = 0; nj < 8; nj++)
#pragma unroll
            for (int u = 0; u < 4; u++) sacc[nj][u] = 0.f;
#pragma unroll
        for (int s = 0; s < 4; s++) {
            uint32_t aq[4];
            ldsm_x4(aq, qs_b + a_off + (uint32_t)(s * 32));
#pragma unroll
            for (int nt = 0; nt < 4; nt++) {
                uint32_t bk[4];
                ldsm_x4(bk, ks_b + (uint32_t)(((nt * 16 + (g >> 1) * 8 + lr) * QSTR
                                               + (g & 1) * 8 + s * 16) * 2));
                mma_f16(sacc[2*nt + 0], aq, &bk[0]);
                mma_f16(sacc[2*nt + 1], aq, &bk[2]);
            }
        }

        float mx0 = -1e30f, mx1 = -1e30f;
#pragma unroll
        for (int nj = 0; nj < 8; nj++) {
            int kc = nj * 8 + 2 * q2;
            bool msk0 = Ms[bb][kc] != 0;
            bool msk1 = Ms[bb][kc + 1] != 0;
            sacc[nj][0] = msk0 ? -1e30f : sacc[nj][0] * 0.125f;
            sacc[nj][1] = msk1 ? -1e30f : sacc[nj][1] * 0.125f;
            sacc[nj][2] = msk0 ? -1e30f : sacc[nj][2] * 0.125f;
            sacc[nj][3] = msk1 ? -1e30f : sacc[nj][3] * 0.125f;
            mx0 = fmaxf(mx0, fmaxf(sacc[nj][0], sacc[nj][1]));
            mx1 = fmaxf(mx1, fmaxf(sacc[nj][2], sacc[nj][3]));
        }
        mx0 = fmaxf(mx0, __shfl_xor_sync(0xffffffffu, mx0, 1));
        mx0 = fmaxf(mx0, __shfl_xor_sync(0xffffffffu, mx0, 2));
        mx1 = fmaxf(mx1, __shfl_xor_sync(0xffffffffu, mx1, 1));
        mx1 = fmaxf(mx1, __shfl_xor_sync(0xffffffffu, mx1, 2));
        float mn0 = fmaxf(m0, mx0), mn1 = fmaxf(m1, mx1);
        float cr0 = __expf(m0 - mn0), cr1 = __expf(m1 - mn1);

        float s0 = 0.f, s1 = 0.f;
#pragma unroll
        for (int nj = 0; nj < 8; nj++) {
            sacc[nj][0] = __expf(sacc[nj][0] - mn0);
            sacc[nj][1] = __expf(sacc[nj][1] - mn0);
            sacc[nj][2] = __expf(sacc[nj][2] - mn1);
            sacc[nj][3] = __expf(sacc[nj][3] - mn1);
            s0 += sacc[nj][0] + sacc[nj][1];
            s1 += sacc[nj][2] + sacc[nj][3];
        }
        s0 += __shfl_xor_sync(0xffffffffu, s0, 1);
        s0 += __shfl_xor_sync(0xffffffffu, s0, 2);
        s1 += __shfl_xor_sync(0xffffffffu, s1, 1);
        s1 += __shfl_xor_sync(0xffffffffu, s1, 2);
        l0 = l0 * cr0 + s0;
        l1 = l1 * cr1 + s1;
        m0 = mn0; m1 = mn1;
#pragma unroll
        for (int nj = 0; nj < 8; nj++) {
            oacc[nj][0] *= cr0; oacc[nj][1] *= cr0;
            oacc[nj][2] *= cr1; oacc[nj][3] *= cr1;
        }

#pragma unroll
        for (int s = 0; s < 4; s++) {
            uint32_t pa[4];
            pa[0] = pack_hf(sacc[2*s][0],   sacc[2*s][1]);
            pa[1] = pack_hf(sacc[2*s][2],   sacc[2*s][3]);
            pa[2] = pack_hf(sacc[2*s+1][0], sacc[2*s+1][1]);
            pa[3] = pack_hf(sacc[2*s+1][2], sacc[2*s+1][3]);
#pragma unroll
            for (int t = 0; t < 4; t++) {
                uint32_t bv[4];
                ldsm_x4_t(bv, vs_b + (uint32_t)(((16 * s + (g & 1) * 8 + lr) * QSTR
                                                 + 8 * (2 * t + (g >> 1))) * 2));
                mma_f16(oacc[2*t + 0], pa, &bv[0]);
                mma_f16(oacc[2*t + 1], pa, &bv[2]);
            }
        }

        __syncthreads();
        if (kt + 2 < NN / 64) {
            load_kv(kt + 2, bb);
        }
        cp_commit();
    }

    float inv0 = (l0 > 0.f) ? (1.f / l0) : 0.f;
    float inv1 = (l1 > 0.f) ? (1.f / l1) : 0.f;
    size_t r0g = (size_t)(b * NN + q0 + 16 * w + gid) * DD + h * HD;
    size_t r1g = r0g + (size_t)8 * DD;
#pragma unroll
    for (int nj = 0; nj < 8; nj++) {
        int col = nj * 8 + 2 * q2;
        *(uint32_t*)(Oh + r0g + col) = pack_hf(oacc[nj][0] * inv0, oacc[nj][1] * inv0);
        *(uint32_t*)(Oh + r1g + col) = pack_hf(oacc[nj][2] * inv1, oacc[nj][3] * inv1);
    }
}

// ---------------- residual add + LayerNorm (warp per row, no barriers) ----------------
__global__ void __launch_bounds__(256) ln_kernel(
    const float* __restrict__ x, const float* __restrict__ res,
    const float* __restrict__ g, const float* __restrict__ bparam,
    float* __restrict__ out,
    __half* __restrict__ outh)
{
    int warp = threadIdx.x >> 5;
    int lane = threadIdx.x & 31;
    int row = blockIdx.x * 8 + warp;
    if (row >= MTOT) return;

    const float4* xr = (const float4*)(x + (size_t)row * DD);
    const float4* rr = res ? (const float4*)(res + (size_t)row * DD) : nullptr;
    float4 v[4];
    float s = 0.f;
#pragma unroll
    for (int k = 0; k < 4; k++) {
        v[k] = xr[lane + 32 * k];
        if (rr) {
            float4 r = rr[lane + 32 * k];
            v[k].x += r.x; v[k].y += r.y; v[k].z += r.z; v[k].w += r.w;
        }
        s += v[k].x + v[k].y + v[k].z + v[k].w;
    }
#pragma unroll
    for (int o = 16; o > 0; o >>= 1) s += __shfl_xor_sync(0xffffffffu, s, o);
    float mu = s * (1.f / DD);
    float q2 = 0.f;
#pragma unroll
    for (int k = 0; k < 4; k++) {
        v[k].x -= mu; v[k].y -= mu; v[k].z -= mu; v[k].w -= mu;
        q2 += v[k].x*v[k].x + v[k].y*v[k].y + v[k].z*v[k].z + v[k].w*v[k].w;
    }
#pragma unroll
    for (int o = 16; o > 0; o >>= 1) q2 += __shfl_xor_sync(0xffffffffu, q2, o);
    float rs = rsqrtf(q2 * (1.f / DD) + 1e-5f);

    float4* outr = (float4*)(out + (size_t)row * DD);
    uint2* outhr = (uint2*)(outh + (size_t)row * DD);
#pragma unroll
    for (int k = 0; k < 4; k++) {
        float4 gv = ((const float4*)g)[lane + 32 * k];
        float4 bv = ((const float4*)bparam)[lane + 32 * k];
        float4 o;
        o.x = v[k].x * rs * gv.x + bv.x;
        o.y = v[k].y * rs * gv.y + bv.y;
        o.z = v[k].z * rs * gv.z + bv.z;
        o.w = v[k].w * rs * gv.w + bv.w;
        outr[lane + 32 * k] = o;
        uint2 hp;
        hp.x = pack_hf(o.x, o.y);
        hp.y = pack_hf(o.z, o.w);
        outhr[lane + 32 * k] = hp;
    }
}

// ---------------- launch ----------------
extern "C" void kernel_launch(void* const* d_in, const int* in_sizes, int n_in,
                              void* d_out, int out_size)
{
    const float* src      = (const float*)d_in[0];
    const unsigned char* kpm = (const unsigned char*)d_in[1];
    const float* embed_W  = (const float*)d_in[2];
    const float* embed_b  = (const float*)d_in[3];
    const float* Wq = (const float*)d_in[4];
    const float* bq = (const float*)d_in[5];
    const float* Wk = (const float*)d_in[6];
    const float* bk = (const float*)d_in[7];
    const float* Wv = (const float*)d_in[8];
    const float* bv = (const float*)d_in[9];
    const float* Wo = (const float*)d_in[10];
    const float* bo = (const float*)d_in[11];
    const float* W1 = (const float*)d_in[12];
    const float* b1 = (const float*)d_in[13];
    const float* W2 = (const float*)d_in[14];
    const float* b2 = (const float*)d_in[15];
    const float* ln1_g = (const float*)d_in[16];
    const float* ln1_b = (const float*)d_in[17];
    const float* ln2_g = (const float*)d_in[18];
    const float* ln2_b = (const float*)d_in[19];
    const float* fin_g = (const float*)d_in[20];
    const float* fin_b = (const float*)d_in[21];
    const float* head_W = (const float*)d_in[22];
    const float* head_b = (const float*)d_in[23];

    float *x, *q, *t;
    cudaGetSymbolAddress((void**)&x, g_x);
    cudaGetSymbolAddress((void**)&q, g_q);
    cudaGetSymbolAddress((void**)&t, g_t);

    __half *qkv, *xh, *th, *ffh, *shp;
    __half *wqkvh, *woh, *w1h, *w2h, *ewh;
    float *bqkv;
    cudaGetSymbolAddress((void**)&qkv, g_qkv);
    cudaGetSymbolAddress((void**)&xh, g_xh);
    cudaGetSymbolAddress((void**)&th, g_th);
    cudaGetSymbolAddress((void**)&ffh, g_ffh);
    cudaGetSymbolAddress((void**)&shp, g_sh);
    cudaGetSymbolAddress((void**)&wqkvh, g_wqkvh);
    cudaGetSymbolAddress((void**)&bqkv, g_bqkv);
    cudaGetSymbolAddress((void**)&woh, g_woh);
    cudaGetSymbolAddress((void**)&w1h, g_w1h);
    cudaGetSymbolAddress((void**)&w2h, g_w2h);
    cudaGetSymbolAddress((void**)&ewh, g_ewh);

    cudaFuncSetAttribute(gemm_hf, cudaFuncAttributeMaxDynamicSharedMemorySize, GB_SMEM);

    const int TS = 256;
    auto blocks = [](size_t n4) { return (int)((n4 + 255) / 256); };
    size_t nQKV = (size_t)LL * 3 * DD * DD / 4;

    int nWo = (int)((size_t)LL * DD * DD / 4);      // 393216
    int nW1 = (int)((size_t)LL * FFD * DD / 4);     // 1572864
    int nW2 = nW1;
    int nEw = DD * DIN / 4;                          // 8192
    int nSrc = MTOT * DIN / 4;                       // 131072
    size_t nMulti = (size_t)nWo + nW1 + nW2 + nEw + nSrc;

    conv_qkv<<<blocks(nQKV), TS>>>(Wq, Wk, Wv, wqkvh, (int)nQKV);
    concat_bias<<<(LL*QKVD + 255)/256, TS>>>(bq, bk, bv, bqkv);
    conv_multi<<<blocks(nMulti), TS>>>(Wo, woh, nWo,
                                       W1, w1h, nW1,
                                       W2, w2h, nW2,
                                       embed_W, ewh, nEw,
                                       src, shp, nSrc);

    dim3 gD(DD/128, MTOT/128);       // 4 x 64
    dim3 gQKV(QKVD/128, MTOT/128);   // 12 x 64
    dim3 gF(FFD/128, MTOT/128);      // 16 x 64
    dim3 gA(NN/64, HH, BB);          // 16 x 8 x 8

    gemm_hf<<<gD, 256, GB_SMEM>>>(MTOT, DD, DIN, shp, ewh,
                                  embed_b, x, xh, 0, 1, 1);

    for (int l = 0; l < LL; l++) {
        size_t offW = (size_t)l * DD * DD;
        size_t offQKV = (size_t)l * QKVD * DD;
        size_t offF = (size_t)l * FFD * DD;

        // fused QKV GEMM -> packed fp16 [M, 1536]
        gemm_hf<<<gQKV, 256, GB_SMEM>>>(MTOT, QKVD, DD, xh,
                                        wqkvh + offQKV,
                                        bqkv + l*QKVD, nullptr, qkv, 0, 0, 1);

        attn_mma<<<gA, 128>>>(qkv, qkv + DD, qkv + 2*DD, kpm, th, QKVD);

        gemm_hf<<<gD, 256, GB_SMEM>>>(MTOT, DD, DD, th, woh + offW,
                                      bo + l*DD, q, nullptr, 0, 1, 0);
        ln_kernel<<<MTOT/8, 256>>>(x, q, ln1_g + l*DD, ln1_b + l*DD, x, xh);

        gemm_hf<<<gF, 256, GB_SMEM>>>(MTOT, FFD, DD, xh, w1h + offF,
                                      b1 + l*FFD, nullptr, ffh, 1, 0, 1);
        gemm_hf<<<gD, 256, GB_SMEM>>>(MTOT, DD, FFD, ffh, w2h + offF,
                                      b2 + l*DD, t, nullptr, 0, 1, 0);
        ln_kernel<<<MTOT/8, 256>>>(x, t, ln2_g + l*DD, ln2_b + l*DD, x, xh);
    }

    head_kernel<<<MTOT/8, 256>>>(x, fin_g, fin_b, head_W, head_b, (float*)d_out);
}

// round 17
// speedup vs baseline: 1.0253x; 1.0095x over previous
#include <cuda_runtime.h>
#include <cuda_fp16.h>
#include <cstdint>
#include <cstddef>

// Problem constants
#define BB    8
#define NN    1024
#define DD    512
#define HH    8
#define HD    64
#define FFD   2048
#define LL    6
#define CC    5
#define DIN   64
#define MTOT  (BB*NN)   // 8192
#define QKVD  (3*DD)    // 1536

// ---------------- static scratch (no allocations allowed) ----------------
__device__ float g_x [MTOT*DD];

// fp16 buffers
__device__ __half g_qkv[(size_t)MTOT*QKVD];   // QKV; also reused for Wo/FF2 fp16 outputs
__device__ __half g_xh [MTOT*DD];
__device__ __half g_th [MTOT*DD];
__device__ __half g_ffh[(size_t)MTOT*FFD];
__device__ __half g_sh [MTOT*DIN];
__device__ __half g_wqkvh[(size_t)LL*QKVD*DD];
__device__ float  g_bqkv [LL*QKVD];
__device__ __half g_woh[LL*DD*DD];
__device__ __half g_w1h[(size_t)LL*FFD*DD];
__device__ __half g_w2h[(size_t)LL*DD*FFD];
__device__ __half g_ewh[DD*DIN];

// ================= helpers =================
__device__ __forceinline__ uint32_t smem_u32(const void* p) {
    uint32_t a;
    asm("{ .reg .u64 t; cvta.to.shared.u64 t, %1; cvt.u32.u64 %0, t; }" : "=r"(a) : "l"(p));
    return a;
}
__device__ __forceinline__ void ldsm_x4(uint32_t* r, uint32_t addr) {
    asm volatile("ldmatrix.sync.aligned.m8n8.x4.shared.b16 {%0,%1,%2,%3}, [%4];"
                 : "=r"(r[0]), "=r"(r[1]), "=r"(r[2]), "=r"(r[3]) : "r"(addr));
}
__device__ __forceinline__ void ldsm_x4_t(uint32_t* r, uint32_t addr) {
    asm volatile("ldmatrix.sync.aligned.m8n8.x4.trans.shared.b16 {%0,%1,%2,%3}, [%4];"
                 : "=r"(r[0]), "=r"(r[1]), "=r"(r[2]), "=r"(r[3]) : "r"(addr));
}
__device__ __forceinline__ void mma_f16(float* d, const uint32_t* a, const uint32_t* b) {
    asm volatile(
        "mma.sync.aligned.m16n8k16.row.col.f32.f16.f16.f32 "
        "{%0,%1,%2,%3}, {%4,%5,%6,%7}, {%8,%9}, {%0,%1,%2,%3};"
        : "+f"(d[0]), "+f"(d[1]), "+f"(d[2]), "+f"(d[3])
        : "r"(a[0]), "r"(a[1]), "r"(a[2]), "r"(a[3]), "r"(b[0]), "r"(b[1]));
}
__device__ __forceinline__ void cpa16(uint32_t dst, const void* src) {
    asm volatile("cp.async.ca.shared.global [%0], [%1], 16;"
                 :: "r"(dst), "l"(__cvta_generic_to_global(src)));
}
__device__ __forceinline__ void cp_commit() {
    asm volatile("cp.async.commit_group;");
}
template<int N> __device__ __forceinline__ void cp_wait() {
    asm volatile("cp.async.wait_group %0;" :: "n"(N));
}
__device__ __forceinline__ uint32_t pack_hf(float a, float b) {
    __half2 p = __floats2half2_rn(a, b);
    return *(uint32_t*)&p;
}

// ---------------- merged fp32 -> fp16 conversion (5 segments in one launch) ----
__global__ void __launch_bounds__(256) conv_multi(
    const float* __restrict__ i0, __half* __restrict__ o0, int n0,
    const float* __restrict__ i1, __half* __restrict__ o1, int n1,
    const float* __restrict__ i2, __half* __restrict__ o2, int n2,
    const float* __restrict__ i3, __half* __restrict__ o3, int n3,
    const float* __restrict__ i4, __half* __restrict__ o4, int n4)
{
    int i = blockIdx.x * blockDim.x + threadIdx.x;
    const float* in; __half* out; int idx;
    if (i < n0)                    { in = i0; out = o0; idx = i; }
    else if ((i -= n0) < n1)       { in = i1; out = o1; idx = i; }
    else if ((i -= n1) < n2)       { in = i2; out = o2; idx = i; }
    else if ((i -= n2) < n3)       { in = i3; out = o3; idx = i; }
    else if ((i -= n3) < n4)       { in = i4; out = o4; idx = i; }
    else return;
    float4 v = ((const float4*)in)[idx];
    uint2 hv;
    hv.x = pack_hf(v.x, v.y);
    hv.y = pack_hf(v.z, v.w);
    ((uint2*)out)[idx] = hv;
}

// ---------------- fused QKV weight convert: [L][3][D][D] from Wq/Wk/Wv ----
__global__ void __launch_bounds__(256) conv_qkv(
    const float* __restrict__ Wq, const float* __restrict__ Wk,
    const float* __restrict__ Wv, __half* __restrict__ out, int n4)
{
    int i = blockIdx.x * blockDim.x + threadIdx.x;
    if (i >= n4) return;
    const int per_mat = DD * DD / 4;
    int l = i / (3 * per_mat);
    int rem = i - l * (3 * per_mat);
    int which = rem / per_mat;
    int r2 = rem - which * per_mat;
    const float* src = (which == 0 ? Wq : (which == 1 ? Wk : Wv)) + (size_t)l * DD * DD;
    float4 v = ((const float4*)src)[r2];
    uint2 hv;
    hv.x = pack_hf(v.x, v.y);
    hv.y = pack_hf(v.z, v.w);
    ((uint2*)out)[i] = hv;
}

// ---------------- concat qkv biases ----------------
__global__ void __launch_bounds__(256) concat_bias(
    const float* __restrict__ bq, const float* __restrict__ bk,
    const float* __restrict__ bv, float* __restrict__ out)
{
    int idx = blockIdx.x * blockDim.x + threadIdx.x;
    if (idx >= LL * QKVD) return;
    int l = idx / QKVD, r = idx % QKVD;
    float v = (r < DD) ? bq[l * DD + r]
            : (r < 2 * DD) ? bk[l * DD + r - DD]
            : bv[l * DD + r - 2 * DD];
    out[idx] = v;
}

// ================== pipelined plain-fp16 GEMM ==================
// BM=128 BN=128 BK=64, 256 threads = 8 warps (4m x 2n), warp tile 32x64.
// 3-stage cp.async pipeline, 108KB SMEM -> 2 CTAs/SM.
#define SSTR    72
#define TILEB   (128*SSTR*2)       // 18432 B
#define STAGEB  (2*TILEB)          // 36864 B
#define NST     3
#define GB_SMEM (NST*STAGEB)       // 110592 B

__global__ void __launch_bounds__(256, 2) gemm_hf(
    int M, int N, int K,
    const __half* __restrict__ Ah,
    const __half* __restrict__ Bh,
    const float* __restrict__ bias,
    float* __restrict__ C,
    __half* __restrict__ Ch,
    int relu, int wf32, int wbf)
{
    extern __shared__ char smem[];
    uint32_t sbase = smem_u32(smem);

    int tid  = threadIdx.x;
    int lane = tid & 31;
    int wid  = tid >> 5;
    int wr   = wid >> 1;
    int wc   = wid & 1;
    int g    = lane >> 3;
    int lr   = lane & 7;

    int row0 = blockIdx.y << 7;
    int col0 = blockIdx.x << 7;

    float acc[2][8][4];
#pragma unroll
    for (int mi = 0; mi < 2; mi++)
#pragma unroll
        for (int ni = 0; ni < 8; ni++)
#pragma unroll
            for (int u = 0; u < 4; u++) acc[mi][ni][u] = 0.f;

    uint32_t a_off = (uint32_t)(((wr * 32 + (g & 1) * 8 + lr) * SSTR + (g >> 1) * 8) * 2);
    uint32_t b_off = (uint32_t)(((wc * 64 + (g >> 1) * 8 + lr) * SSTR + (g & 1) * 8) * 2);

    const int nch = K >> 6;

    auto load_chunk = [&](int c, int stg) {
        uint32_t sb = sbase + (uint32_t)stg * STAGEB;
        int k0 = c << 6;
#pragma unroll
        for (int t = 0; t < 4; t++) {
            int i = tid + 256 * t;
            int row = i >> 3;
            int c8  = (i & 7) << 3;
            uint32_t doff = (uint32_t)((row * SSTR + c8) * 2);
            cpa16(sb + doff,         Ah + (size_t)(row0 + row) * K + k0 + c8);
            cpa16(sb + TILEB + doff, Bh + (size_t)(col0 + row) * K + k0 + c8);
        }
    };

#pragma unroll
    for (int s = 0; s < NST - 1; s++) {
        if (s < nch) load_chunk(s, s);
        cp_commit();
    }

    int stg = 0;
    for (int c = 0; c < nch; c++) {
        cp_wait<NST - 2>();
        __syncthreads();
        int pf = c + NST - 1;
        int pstg = stg + NST - 1; if (pstg >= NST) pstg -= NST;
        if (pf < nch) load_chunk(pf, pstg);
        cp_commit();

        uint32_t base = sbase + (uint32_t)stg * STAGEB;
#pragma unroll
        for (int s = 0; s < 4; s++) {
            uint32_t scol = (uint32_t)(s * 32);
            uint32_t ah[2][4], bf[4][4];
#pragma unroll
            for (int mi = 0; mi < 2; mi++) {
                uint32_t ao = base + a_off + scol + (uint32_t)(mi * 16 * SSTR * 2);
                ldsm_x4(ah[mi], ao);
            }
#pragma unroll
            for (int nj = 0; nj < 4; nj++) {
                uint32_t bo = base + TILEB + b_off + scol + (uint32_t)(nj * 16 * SSTR * 2);
                ldsm_x4(bf[nj], bo);
            }
#pragma unroll
            for (int mi = 0; mi < 2; mi++)
#pragma unroll
                for (int nj = 0; nj < 4; nj++) {
                    mma_f16(acc[mi][2*nj + 0], ah[mi], &bf[nj][0]);
                    mma_f16(acc[mi][2*nj + 1], ah[mi], &bf[nj][2]);
                }
        }
        if (++stg == NST) stg = 0;
    }

    int gid = lane >> 2, qid = lane & 3;
#pragma unroll
    for (int mi = 0; mi < 2; mi++) {
#pragma unroll
        for (int nj = 0; nj < 8; nj++) {
            int col = col0 + wc * 64 + nj * 8 + qid * 2;
            float b0 = bias[col], b1 = bias[col + 1];
#pragma unroll
            for (int half = 0; half < 2; half++) {
                int row = row0 + wr * 32 + mi * 16 + gid + half * 8;
                float v0 = acc[mi][nj][half * 2 + 0] + b0;
                float v1 = acc[mi][nj][half * 2 + 1] + b1;
                if (relu) { v0 = fmaxf(v0, 0.f); v1 = fmaxf(v1, 0.f); }
                size_t off = (size_t)row * N + col;
                if (wf32) *(float2*)(C + off) = make_float2(v0, v1);
                if (wbf) {
                    uint32_t hp = pack_hf(v0, v1);
                    *(uint32_t*)(Ch + off) = hp;
                }
            }
        }
    }
}

// ---------------- head with fused final LayerNorm (warp per row) ----------------
__global__ void __launch_bounds__(256) head_kernel(
    const float* __restrict__ x, const float* __restrict__ fg,
    const float* __restrict__ fb, const float* __restrict__ W,
    const float* __restrict__ b, float* __restrict__ out)
{
    int warp = threadIdx.x >> 5;
    int lane = threadIdx.x & 31;
    int row = blockIdx.x * 8 + warp;
    if (row >= MTOT) return;

    const float4* xr = (const float4*)(x + (size_t)row * DD);
    float4 xv[4];
    float s = 0.f;
#pragma unroll
    for (int k = 0; k < 4; k++) {
        xv[k] = xr[lane + 32 * k];
        s += xv[k].x + xv[k].y + xv[k].z + xv[k].w;
    }
#pragma unroll
    for (int o = 16; o > 0; o >>= 1) s += __shfl_xor_sync(0xffffffffu, s, o);
    float mu = s * (1.f / DD);
    float q2 = 0.f;
#pragma unroll
    for (int k = 0; k < 4; k++) {
        xv[k].x -= mu; xv[k].y -= mu; xv[k].z -= mu; xv[k].w -= mu;
        q2 += xv[k].x*xv[k].x + xv[k].y*xv[k].y + xv[k].z*xv[k].z + xv[k].w*xv[k].w;
    }
#pragma unroll
    for (int o = 16; o > 0; o >>= 1) q2 += __shfl_xor_sync(0xffffffffu, q2, o);
    float rs = rsqrtf(q2 * (1.f / DD) + 1e-5f);
#pragma unroll
    for (int k = 0; k < 4; k++) {
        float4 gv = ((const float4*)fg)[lane + 32 * k];
        float4 bv = ((const float4*)fb)[lane + 32 * k];
        xv[k].x = xv[k].x * rs * gv.x + bv.x;
        xv[k].y = xv[k].y * rs * gv.y + bv.y;
        xv[k].z = xv[k].z * rs * gv.z + bv.z;
        xv[k].w = xv[k].w * rs * gv.w + bv.w;
    }

    float sums[CC];
#pragma unroll
    for (int c = 0; c < CC; c++) {
        const float4* wr = (const float4*)(W + (size_t)c * DD);
        float sv = 0.f;
#pragma unroll
        for (int k = 0; k < 4; k++) {
            float4 wv = wr[lane + 32 * k];
            sv += xv[k].x * wv.x + xv[k].y * wv.y + xv[k].z * wv.z + xv[k].w * wv.w;
        }
#pragma unroll
        for (int o = 16; o > 0; o >>= 1) sv += __shfl_xor_sync(0xffffffffu, sv, o);
        sums[c] = sv;
    }
    if (lane == 0) {
#pragma unroll
        for (int c = 0; c < CC; c++) out[(size_t)row * CC + c] = sums[c] + b[c];
    }
}

// ================== tensor-core flash attention (fp16 MMA) ==================
// CTA = 64 queries of one (b,h), 128 threads (4 warps),
// double-buffered 64-key K/V tiles via cp.async.
#define QSTR 72

__global__ void __launch_bounds__(128) attn_mma(
    const __half* __restrict__ Q, const __half* __restrict__ K,
    const __half* __restrict__ V, const unsigned char* __restrict__ kpm,
    __half* __restrict__ Oh, int ldq)
{
    __shared__ __half Qs[64][QSTR];
    __shared__ __half Ks[2][64][QSTR];
    __shared__ __half Vs[2][64][QSTR];
    __shared__ unsigned char Ms[2][64];

    int b = blockIdx.z, h = blockIdx.y, q0 = blockIdx.x << 6;
    int tid = threadIdx.x;
    int w    = tid >> 5;
    int lane = tid & 31;
    int g    = lane >> 3;
    int lr   = lane & 7;
    int gid  = lane >> 2;
    int q2   = lane & 3;

    uint32_t qs_b  = smem_u32(&Qs[0][0]);
    uint32_t ks_b0 = smem_u32(&Ks[0][0][0]);
    uint32_t vs_b0 = smem_u32(&Vs[0][0][0]);
    const uint32_t KVBUF = (uint32_t)(64 * QSTR * 2);

    auto load_kv = [&](int kt, int bb) {
#pragma unroll
        for (int t = 0; t < 4; t++) {
            int i = tid + 128 * t;
            int row = i >> 3;
            int c8  = (i & 7) << 3;
            size_t gsrc = (size_t)(b * NN + kt * 64 + row) * ldq + h * HD + c8;
            uint32_t doff = (uint32_t)((row * QSTR + c8) * 2);
            cpa16(ks_b0 + bb * KVBUF + doff, K + gsrc);
            cpa16(vs_b0 + bb * KVBUF + doff, V + gsrc);
        }
        if (tid < 4)
            cpa16(smem_u32(&Ms[bb][0]) + tid * 16, kpm + b * NN + kt * 64 + tid * 16);
    };

#pragma unroll
    for (int t = 0; t < 4; t++) {
        int i = tid + 128 * t;
        int row = i >> 3;
        int c8  = (i & 7) << 3;
        cpa16(qs_b + (uint32_t)((row * QSTR + c8) * 2),
              Q + (size_t)(b * NN + q0 + row) * ldq + h * HD + c8);
    }
    load_kv(0, 0);
    cp_commit();
    load_kv(1, 1);
    cp_commit();

    float oacc[8][4];
#pragma unroll
    for (int nj = 0; nj < 8; nj++)
#pragma unroll
        for (int u = 0; u < 4; u++) oacc[nj][u] = 0.f;
    float m0 = -1e30f, m1 = -1e30f, l0 = 0.f, l1 = 0.f;

    uint32_t a_off = (uint32_t)(((16 * w + (g & 1) * 8 + lr) * QSTR + (g >> 1) * 8) * 2);

    for (int kt = 0; kt < NN / 64; kt++) {
        cp_wait<1>();
        __syncthreads();
        int bb = kt & 1;
        uint32_t ks_b = ks_b0 + bb * KVBUF;
        uint32_t vs_b = vs_b0 + bb * KVBUF;

        float sacc[8][4];
#pragma unroll
        for (int nj = 0; nj < 8; nj++)
#pragma unroll
            for (int u = 0; u < 4; u++) sacc[nj][u] = 0.f;
#pragma unroll
        for (int s = 0; s < 4; s++) {
            uint32_t aq[4];
            ldsm_x4(aq, qs_b + a_off + (uint32_t)(s * 32));
#pragma unroll
            for (int nt = 0; nt < 4; nt++) {
                uint32_t bk[4];
                ldsm_x4(bk, ks_b + (uint32_t)(((nt * 16 + (g >> 1) * 8 + lr) * QSTR
                                               + (g & 1) * 8 + s * 16) * 2));
                mma_f16(sacc[2*nt + 0], aq, &bk[0]);
                mma_f16(sacc[2*nt + 1], aq, &bk[2]);
            }
        }

        float mx0 = -1e30f, mx1 = -1e30f;
#pragma unroll
        for (int nj = 0; nj < 8; nj++) {
            int kc = nj * 8 + 2 * q2;
            bool msk0 = Ms[bb][kc] != 0;
            bool msk1 = Ms[bb][kc + 1] != 0;
            sacc[nj][0] = msk0 ? -1e30f : sacc[nj][0] * 0.125f;
            sacc[nj][1] = msk1 ? -1e30f : sacc[nj][1] * 0.125f;
            sacc[nj][2] = msk0 ? -1e30f : sacc[nj][2] * 0.125f;
            sacc[nj][3] = msk1 ? -1e30f : sacc[nj][3] * 0.125f;
            mx0 = fmaxf(mx0, fmaxf(sacc[nj][0], sacc[nj][1]));
            mx1 = fmaxf(mx1, fmaxf(sacc[nj][2], sacc[nj][3]));
        }
        mx0 = fmaxf(mx0, __shfl_xor_sync(0xffffffffu, mx0, 1));
        mx0 = fmaxf(mx0, __shfl_xor_sync(0xffffffffu, mx0, 2));
        mx1 = fmaxf(mx1, __shfl_xor_sync(0xffffffffu, mx1, 1));
        mx1 = fmaxf(mx1, __shfl_xor_sync(0xffffffffu, mx1, 2));
        float mn0 = fmaxf(m0, mx0), mn1 = fmaxf(m1, mx1);
        float cr0 = __expf(m0 - mn0), cr1 = __expf(m1 - mn1);

        float s0 = 0.f, s1 = 0.f;
#pragma unroll
        for (int nj = 0; nj < 8; nj++) {
            sacc[nj][0] = __expf(sacc[nj][0] - mn0);
            sacc[nj][1] = __expf(sacc[nj][1] - mn0);
            sacc[nj][2] = __expf(sacc[nj][2] - mn1);
            sacc[nj][3] = __expf(sacc[nj][3] - mn1);
            s0 += sacc[nj][0] + sacc[nj][1];
            s1 += sacc[nj][2] + sacc[nj][3];
        }
        s0 += __shfl_xor_sync(0xffffffffu, s0, 1);
        s0 += __shfl_xor_sync(0xffffffffu, s0, 2);
        s1 += __shfl_xor_sync(0xffffffffu, s1, 1);
        s1 += __shfl_xor_sync(0xffffffffu, s1, 2);
        l0 = l0 * cr0 + s0;
        l1 = l1 * cr1 + s1;
        m0 = mn0; m1 = mn1;
#pragma unroll
        for (int nj = 0; nj < 8; nj++) {
            oacc[nj][0] *= cr0; oacc[nj][1] *= cr0;
            oacc[nj][2] *= cr1; oacc[nj][3] *= cr1;
        }

#pragma unroll
        for (int s = 0; s < 4; s++) {
            uint32_t pa[4];
            pa[0] = pack_hf(sacc[2*s][0],   sacc[2*s][1]);
            pa[1] = pack_hf(sacc[2*s][2],   sacc[2*s][3]);
            pa[2] = pack_hf(sacc[2*s+1][0], sacc[2*s+1][1]);
            pa[3] = pack_hf(sacc[2*s+1][2], sacc[2*s+1][3]);
#pragma unroll
            for (int t = 0; t < 4; t++) {
                uint32_t bv[4];
                ldsm_x4_t(bv, vs_b + (uint32_t)(((16 * s + (g & 1) * 8 + lr) * QSTR
                                                 + 8 * (2 * t + (g >> 1))) * 2));
                mma_f16(oacc[2*t + 0], pa, &bv[0]);
                mma_f16(oacc[2*t + 1], pa, &bv[2]);
            }
        }

        __syncthreads();
        if (kt + 2 < NN / 64) {
            load_kv(kt + 2, bb);
        }
        cp_commit();
    }

    float inv0 = (l0 > 0.f) ? (1.f / l0) : 0.f;
    float inv1 = (l1 > 0.f) ? (1.f / l1) : 0.f;
    size_t r0g = (size_t)(b * NN + q0 + 16 * w + gid) * DD + h * HD;
    size_t r1g = r0g + (size_t)8 * DD;
#pragma unroll
    for (int nj = 0; nj < 8; nj++) {
        int col = nj * 8 + 2 * q2;
        *(uint32_t*)(Oh + r0g + col) = pack_hf(oacc[nj][0] * inv0, oacc[nj][1] * inv0);
        *(uint32_t*)(Oh + r1g + col) = pack_hf(oacc[nj][2] * inv1, oacc[nj][3] * inv1);
    }
}

// ---------------- residual(fp16) add + LayerNorm (warp per row, no barriers) ----
__global__ void __launch_bounds__(256) ln_kernel(
    const float* __restrict__ x, const __half* __restrict__ res,
    const float* __restrict__ g, const float* __restrict__ bparam,
    float* __restrict__ out,
    __half* __restrict__ outh)
{
    int warp = threadIdx.x >> 5;
    int lane = threadIdx.x & 31;
    int row = blockIdx.x * 8 + warp;
    if (row >= MTOT) return;

    const float4* xr = (const float4*)(x + (size_t)row * DD);
    const uint2* rr = (const uint2*)(res + (size_t)row * DD);
    float4 v[4];
    float s = 0.f;
#pragma unroll
    for (int k = 0; k < 4; k++) {
        v[k] = xr[lane + 32 * k];
        uint2 hp = rr[lane + 32 * k];
        float2 f0 = __half22float2(*(__half2*)&hp.x);
        float2 f1 = __half22float2(*(__half2*)&hp.y);
        v[k].x += f0.x; v[k].y += f0.y; v[k].z += f1.x; v[k].w += f1.y;
        s += v[k].x + v[k].y + v[k].z + v[k].w;
    }
#pragma unroll
    for (int o = 16; o > 0; o >>= 1) s += __shfl_xor_sync(0xffffffffu, s, o);
    float mu = s * (1.f / DD);
    float q2 = 0.f;
#pragma unroll
    for (int k = 0; k < 4; k++) {
        v[k].x -= mu; v[k].y -= mu; v[k].z -= mu; v[k].w -= mu;
        q2 += v[k].x*v[k].x + v[k].y*v[k].y + v[k].z*v[k].z + v[k].w*v[k].w;
    }
#pragma unroll
    for (int o = 16; o > 0; o >>= 1) q2 += __shfl_xor_sync(0xffffffffu, q2, o);
    float rs = rsqrtf(q2 * (1.f / DD) + 1e-5f);

    float4* outr = (float4*)(out + (size_t)row * DD);
    uint2* outhr = (uint2*)(outh + (size_t)row * DD);
#pragma unroll
    for (int k = 0; k < 4; k++) {
        float4 gv = ((const float4*)g)[lane + 32 * k];
        float4 bv = ((const float4*)bparam)[lane + 32 * k];
        float4 o;
        o.x = v[k].x * rs * gv.x + bv.x;
        o.y = v[k].y * rs * gv.y + bv.y;
        o.z = v[k].z * rs * gv.z + bv.z;
        o.w = v[k].w * rs * gv.w + bv.w;
        outr[lane + 32 * k] = o;
        uint2 hp;
        hp.x = pack_hf(o.x, o.y);
        hp.y = pack_hf(o.z, o.w);
        outhr[lane + 32 * k] = hp;
    }
}

// ---------------- launch ----------------
extern "C" void kernel_launch(void* const* d_in, const int* in_sizes, int n_in,
                              void* d_out, int out_size)
{
    const float* src      = (const float*)d_in[0];
    const unsigned char* kpm = (const unsigned char*)d_in[1];
    const float* embed_W  = (const float*)d_in[2];
    const float* embed_b  = (const float*)d_in[3];
    const float* Wq = (const float*)d_in[4];
    const float* bq = (const float*)d_in[5];
    const float* Wk = (const float*)d_in[6];
    const float* bk = (const float*)d_in[7];
    const float* Wv = (const float*)d_in[8];
    const float* bv = (const float*)d_in[9];
    const float* Wo = (const float*)d_in[10];
    const float* bo = (const float*)d_in[11];
    const float* W1 = (const float*)d_in[12];
    const float* b1 = (const float*)d_in[13];
    const float* W2 = (const float*)d_in[14];
    const float* b2 = (const float*)d_in[15];
    const float* ln1_g = (const float*)d_in[16];
    const float* ln1_b = (const float*)d_in[17];
    const float* ln2_g = (const float*)d_in[18];
    const float* ln2_b = (const float*)d_in[19];
    const float* fin_g = (const float*)d_in[20];
    const float* fin_b = (const float*)d_in[21];
    const float* head_W = (const float*)d_in[22];
    const float* head_b = (const float*)d_in[23];

    float *x;
    cudaGetSymbolAddress((void**)&x, g_x);

    __half *qkv, *xh, *th, *ffh, *shp;
    __half *wqkvh, *woh, *w1h, *w2h, *ewh;
    float *bqkv;
    cudaGetSymbolAddress((void**)&qkv, g_qkv);
    cudaGetSymbolAddress((void**)&xh, g_xh);
    cudaGetSymbolAddress((void**)&th, g_th);
    cudaGetSymbolAddress((void**)&ffh, g_ffh);
    cudaGetSymbolAddress((void**)&shp, g_sh);
    cudaGetSymbolAddress((void**)&wqkvh, g_wqkvh);
    cudaGetSymbolAddress((void**)&bqkv, g_bqkv);
    cudaGetSymbolAddress((void**)&woh, g_woh);
    cudaGetSymbolAddress((void**)&w1h, g_w1h);
    cudaGetSymbolAddress((void**)&w2h, g_w2h);
    cudaGetSymbolAddress((void**)&ewh, g_ewh);

    cudaFuncSetAttribute(gemm_hf, cudaFuncAttributeMaxDynamicSharedMemorySize, GB_SMEM);

    const int TS = 256;
    auto blocks = [](size_t n4) { return (int)((n4 + 255) / 256); };
    size_t nQKV = (size_t)LL * 3 * DD * DD / 4;

    int nWo = (int)((size_t)LL * DD * DD / 4);
    int nW1 = (int)((size_t)LL * FFD * DD / 4);
    int nW2 = nW1;
    int nEw = DD * DIN / 4;
    int nSrc = MTOT * DIN / 4;
    size_t nMulti = (size_t)nWo + nW1 + nW2 + nEw + nSrc;

    conv_qkv<<<blocks(nQKV), TS>>>(Wq, Wk, Wv, wqkvh, (int)nQKV);
    concat_bias<<<(LL*QKVD + 255)/256, TS>>>(bq, bk, bv, bqkv);
    conv_multi<<<blocks(nMulti), TS>>>(Wo, woh, nWo,
                                       W1, w1h, nW1,
                                       W2, w2h, nW2,
                                       embed_W, ewh, nEw,
                                       src, shp, nSrc);

    dim3 gD(DD/128, MTOT/128);       // 4 x 64
    dim3 gQKV(QKVD/128, MTOT/128);   // 12 x 64
    dim3 gF(FFD/128, MTOT/128);      // 16 x 64
    dim3 gA(NN/64, HH, BB);          // 16 x 8 x 8

    // fp16 branch buffer: reuse the (idle-between-uses) qkv region
    __half* branch = qkv;

    gemm_hf<<<gD, 256, GB_SMEM>>>(MTOT, DD, DIN, shp, ewh,
                                  embed_b, x, xh, 0, 1, 1);

    for (int l = 0; l < LL; l++) {
        size_t offW = (size_t)l * DD * DD;
        size_t offQKV = (size_t)l * QKVD * DD;
        size_t offF = (size_t)l * FFD * DD;

        // fused QKV GEMM -> packed fp16 [M, 1536]
        gemm_hf<<<gQKV, 256, GB_SMEM>>>(MTOT, QKVD, DD, xh,
                                        wqkvh + offQKV,
                                        bqkv + l*QKVD, nullptr, qkv, 0, 0, 1);

        attn_mma<<<gA, 128>>>(qkv, qkv + DD, qkv + 2*DD, kpm, th, QKVD);

        // Wo-proj -> fp16 branch (qkv region is free after attention)
        gemm_hf<<<gD, 256, GB_SMEM>>>(MTOT, DD, DD, th, woh + offW,
                                      bo + l*DD, nullptr, branch, 0, 0, 1);
        ln_kernel<<<MTOT/8, 256>>>(x, branch, ln1_g + l*DD, ln1_b + l*DD, x, xh);

        gemm_hf<<<gF, 256, GB_SMEM>>>(MTOT, FFD, DD, xh, w1h + offF,
                                      b1 + l*FFD, nullptr, ffh, 1, 0, 1);
        // FF2 -> fp16 branch
        gemm_hf<<<gD, 256, GB_SMEM>>>(MTOT, DD, FFD, ffh, w2h + offF,
                                      b2 + l*DD, nullptr, branch, 0, 0, 1);
        ln_kernel<<<MTOT/8, 256>>>(x, branch, ln2_g + l*DD, ln2_b + l*DD, x, xh);
    }

    head_kernel<<<MTOT/8, 256>>>(x, fin_g, fin_b, head_W, head_b, (float*)d_out);
}